// round 1
// baseline (speedup 1.0000x reference)
#include <cuda_runtime.h>
#include <math.h>

#define NMOL 256
#define NPER 32
#define NNODE 8192
#define EPM 992                  // 32*31 edges per molecule
#define ETOT (NMOL*EPM)          // 253952
#define SD 256
#define ED 32
#define MSG_IN 546
#define MSG_OUT 353

// e scratch: lives in global (L2-resident, 32.5MB). Sanctioned __device__ array.
__device__ float g_e[(long)ETOT*ED];

struct SM {
    float s  [NPER][SD];   // node scalar features
    float P  [NPER][SD];   // s @ W1a   (per-src part)
    float Q  [NPER][SD];   // s @ W1b + b1 (per-tgt part)
    float S0 [NPER][SD];   // sum of hdn over incoming edges (per tgt)
    float hdn[NPER][SD];   // hidden activations for current tgt j
    float W1c[ED][SD];     // e-part of W1 (staged per layer)
    float esm[NPER][ED];   // e rows for current tgt j
    float pos [NPER][3];
    float npos[NPER][3];   // pos delta accumulator
    float dbuf[NPER];
    float abuf[NPER];
    float rnb [NPER][3];
    float w2p [SD];
    float pdpart[8][3];
};

__device__ __forceinline__ float silu_f(float v){
    return v * (1.0f / (1.0f + __expf(-v)));
}

__global__ void __launch_bounds__(256,1) dec_kernel(
    const float* __restrict__ x,   const float* __restrict__ z,
    const float* __restrict__ rot, const float* __restrict__ eattr,
    const float* __restrict__ Wam, const float* __restrict__ bam,
    const float* __restrict__ Wbm, const float* __restrict__ bbm,
    const float* __restrict__ gW1, const float* __restrict__ gb1,
    const float* __restrict__ gW2, const float* __restrict__ gb2,
    const float* __restrict__ Wh1, const float* __restrict__ bh1,
    const float* __restrict__ Wh2, const float* __restrict__ bh2,
    const float* __restrict__ We1, const float* __restrict__ be1,
    const float* __restrict__ We2, const float* __restrict__ be2,
    float* __restrict__ outA, float* __restrict__ outB, float* __restrict__ outP)
{
    extern __shared__ float smraw[];
    SM* sm = (SM*)smraw;
    const int tid  = threadIdx.x;
    const int lane = tid & 31;
    const int wrp  = tid >> 5;
    const int mol  = blockIdx.x;
    const int nodeBase = mol * NPER;
    const long ebase   = (long)mol * EPM;
    const int c = tid;   // column owned by this thread (0..255)

    // ------------------------------------------------------------------
    // Embed: h = [x,z] @ Wam + bam ; s = h[:,:256]; pos = rot @ h[:,256:259]
    // ------------------------------------------------------------------
    {
        float* xz = &sm->hdn[0][0];                 // reuse: 32*80 floats
        for (int idx = tid; idx < NPER*80; idx += 256){
            int i = idx / 80, k = idx % 80;
            xz[idx] = (k < 16) ? x[(nodeBase+i)*16 + k]
                               : z[(nodeBase+i)*64 + (k-16)];
        }
        __syncthreads();
        float acc[NPER];
#pragma unroll
        for (int i=0;i<NPER;i++) acc[i]=0.f;
        for (int kg=0; kg<20; kg++){
            float w0=Wam[(4*kg+0)*259+c], w1=Wam[(4*kg+1)*259+c];
            float w2v=Wam[(4*kg+2)*259+c], w3=Wam[(4*kg+3)*259+c];
#pragma unroll
            for (int i=0;i<NPER;i++){
                float4 v = ((const float4*)xz)[i*20+kg];
                acc[i] += v.x*w0 + v.y*w1 + v.z*w2v + v.w*w3;
            }
        }
        float b = bam[c];
#pragma unroll
        for (int i=0;i<NPER;i++) sm->s[i][c] = acc[i] + b;
        if (tid < 96){                                // pos3 into npos (tmp)
            int i = tid/3, cc = tid%3;
            float a = bam[256+cc];
            for (int k=0;k<80;k++) a += xz[i*80+k]*Wam[k*259+256+cc];
            sm->npos[i][cc] = a;
        }
        __syncthreads();
        if (tid < 96){
            int i = tid/3, cc = tid%3;
            float p = 0.f;
#pragma unroll
            for (int q=0;q<3;q++) p += rot[mol*9 + cc*3 + q]*sm->npos[i][q];
            sm->pos[i][cc] = p;
        }
    }

    // ------------------------------------------------------------------
    // e init: e = edge_attr @ Wbm + bbm   (into global scratch)
    // ------------------------------------------------------------------
    for (int idx = tid; idx < EPM*ED; idx += 256){
        int eL = idx >> 5, k = idx & 31;
        const float* ea = &eattr[(ebase+eL)*5];
        float a = bbm[k];
#pragma unroll
        for (int q=0;q<5;q++) a += ea[q]*Wbm[q*ED+k];
        g_e[(ebase+eL)*ED + k] = a;
    }
    __syncthreads();

    // ------------------------------------------------------------------
    // 5 message-passing layers
    // ------------------------------------------------------------------
    for (int l=0; l<5; l++){
        const float* W1 = gW1 + (long)l*MSG_IN*SD;
        const float* b1 = gb1 + l*SD;
        const float* W2 = gW2 + (long)l*SD*MSG_OUT;
        const float* b2 = gb2 + l*MSG_OUT;

        // stage W1c (rows 512..543), w2p (col 320 of W2), zero npos
        for (int idx = tid; idx < ED*SD; idx += 256)
            sm->W1c[idx>>8][idx&255] = W1[512*SD + idx];
        sm->w2p[c] = W2[c*MSG_OUT + 320];
        if (tid < 96) sm->npos[tid/3][tid%3] = 0.f;
        __syncthreads();

        // P = s@W1a ; Q = s@W1b + b1   (thread c owns column c, 32 rows each)
        {
            float accP[NPER], accQ[NPER];
#pragma unroll
            for (int i=0;i<NPER;i++){ accP[i]=0.f; accQ[i]=0.f; }
            for (int kg=0; kg<64; kg++){
                float wa0=W1[(4*kg+0)*SD+c], wa1=W1[(4*kg+1)*SD+c];
                float wa2=W1[(4*kg+2)*SD+c], wa3=W1[(4*kg+3)*SD+c];
                float wb0=W1[(256+4*kg+0)*SD+c], wb1=W1[(256+4*kg+1)*SD+c];
                float wb2=W1[(256+4*kg+2)*SD+c], wb3=W1[(256+4*kg+3)*SD+c];
#pragma unroll
                for (int i=0;i<NPER;i++){
                    float4 v = ((const float4*)&sm->s[i][0])[kg];
                    accP[i] += v.x*wa0 + v.y*wa1 + v.z*wa2 + v.w*wa3;
                    accQ[i] += v.x*wb0 + v.y*wb1 + v.z*wb2 + v.w*wb3;
                }
            }
            float bb = b1[c];
#pragma unroll
            for (int i=0;i<NPER;i++){ sm->P[i][c]=accP[i]; sm->Q[i][c]=accQ[i]+bb; }
        }
        __syncthreads();

        const float w1d = W1[544*SD+c];
        const float w1e = W1[545*SD+c];
        const float b2p = __ldg(&b2[320]);

        for (int j=0; j<NPER; j++){
            // [A] fold prev pdpart into npos; stage e rows + geometry
            if (j>0 && tid<3){
                float sum=0.f;
#pragma unroll
                for (int w=0;w<8;w++) sum += sm->pdpart[w][tid];
                sm->npos[j-1][tid] += sum;
            }
            for (int idx = tid; idx < NPER*ED; idx += 256){
                int i = idx>>5, k = idx&31;
                float v = 0.f;
                if (i != j){
                    int eL = i*31 + j - (j>i);
                    v = g_e[(ebase+eL)*ED + k];
                }
                sm->esm[i][k] = v;
            }
            if (tid < NPER){
                int i = tid;
                float pix=sm->pos[i][0], piy=sm->pos[i][1], piz=sm->pos[i][2];
                float pjx=sm->pos[j][0], pjy=sm->pos[j][1], pjz=sm->pos[j][2];
                float rx=pjx-pix, ry=pjy-piy, rz=pjz-piz;
                float rr = rx*rx + ry*ry + rz*rz;
                float d  = sqrtf(fmaxf(rr, 1e-6f));
                float inv = 1.f/(1.f + d);
                sm->dbuf[i] = d;
                sm->abuf[i] = pix*pjx + piy*pjy + piz*pjz;
                if (i == j){ rx=0.f; ry=0.f; rz=0.f; }
                sm->rnb[i][0]=rx*inv; sm->rnb[i][1]=ry*inv; sm->rnb[i][2]=rz*inv;
            }
            __syncthreads();

            // [B] hdn = silu(P[i]+Q[j]+e@W1c+d*w1d+a*w1e) ; S0[j] = sum_i hdn
            {
                float acc[NPER];
                float qj = sm->Q[j][c];
#pragma unroll
                for (int i=0;i<NPER;i++)
                    acc[i] = sm->P[i][c] + qj + sm->dbuf[i]*w1d + sm->abuf[i]*w1e;
#pragma unroll
                for (int kg=0; kg<8; kg++){
                    float w0=sm->W1c[4*kg+0][c], w1=sm->W1c[4*kg+1][c];
                    float w2v=sm->W1c[4*kg+2][c], w3=sm->W1c[4*kg+3][c];
#pragma unroll
                    for (int i=0;i<NPER;i++){
                        float4 e4 = ((const float4*)&sm->esm[i][0])[kg];
                        acc[i] += e4.x*w0 + e4.y*w1 + e4.z*w2v + e4.w*w3;
                    }
                }
                float s0 = 0.f;
#pragma unroll
                for (int i=0;i<NPER;i++){
                    float h = (i==j) ? 0.f : silu_f(acc[i]);
                    sm->hdn[i][c] = h;
                    s0 += h;
                }
                sm->S0[j][c] = s0;
            }
            __syncthreads();

            // [C1] pos scalars: t_e = hdn.w2p ; pdpart = sum rn*(t+b2p)
            {
                float pdx=0.f, pdy=0.f, pdz=0.f;
#pragma unroll
                for (int r=0;r<4;r++){
                    int i = wrp + 8*r;
                    float part = 0.f;
#pragma unroll
                    for (int m=0;m<8;m++)
                        part += sm->hdn[i][lane+32*m] * sm->w2p[lane+32*m];
#pragma unroll
                    for (int off=16; off>0; off>>=1)
                        part += __shfl_xor_sync(0xffffffffu, part, off);
                    if (lane==0){
                        float t = part + b2p;
                        pdx += sm->rnb[i][0]*t;
                        pdy += sm->rnb[i][1]*t;
                        pdz += sm->rnb[i][2]*t;
                    }
                }
                if (lane==0){ sm->pdpart[wrp][0]=pdx; sm->pdpart[wrp][1]=pdy; sm->pdpart[wrp][2]=pdz; }
            }
            // [C2] e update: e += hdn @ W2e + b2e  (warp: k=lane, 4 rows each)
            {
                const int k = lane, g = wrp;
                const int i0=g, i1=g+8, i2=g+16, i3=g+24;
                float bk = __ldg(&b2[321+k]);
                float a0=bk, a1=bk, a2=bk, a3=bk;
#pragma unroll 8
                for (int c4=0; c4<64; c4++){
                    float4 h0 = ((const float4*)&sm->hdn[i0][0])[c4];
                    float4 h1 = ((const float4*)&sm->hdn[i1][0])[c4];
                    float4 h2 = ((const float4*)&sm->hdn[i2][0])[c4];
                    float4 h3 = ((const float4*)&sm->hdn[i3][0])[c4];
                    float w0 = W2[(4*c4+0)*MSG_OUT + 321 + k];
                    float w1 = W2[(4*c4+1)*MSG_OUT + 321 + k];
                    float w2v= W2[(4*c4+2)*MSG_OUT + 321 + k];
                    float w3 = W2[(4*c4+3)*MSG_OUT + 321 + k];
                    a0 += h0.x*w0 + h0.y*w1 + h0.z*w2v + h0.w*w3;
                    a1 += h1.x*w0 + h1.y*w1 + h1.z*w2v + h1.w*w3;
                    a2 += h2.x*w0 + h2.y*w1 + h2.z*w2v + h2.w*w3;
                    a3 += h3.x*w0 + h3.y*w1 + h3.z*w2v + h3.w*w3;
                }
                float accs[4] = {a0,a1,a2,a3};
#pragma unroll
                for (int r=0;r<4;r++){
                    int i = g + 8*r;
                    if (i != j){
                        int eL = i*31 + j - (j>i);
                        g_e[(ebase+eL)*ED + k] = accs[r] + sm->esm[i][k];
                    }
                }
            }
            __syncthreads();
        } // j

        if (tid<3){
            float sum=0.f;
#pragma unroll
            for (int w=0;w<8;w++) sum += sm->pdpart[w][tid];
            sm->npos[31][tid] += sum;
        }
        // s += (S0 @ W2s)/31 + b2s
        {
            float acc[NPER];
#pragma unroll
            for (int i=0;i<NPER;i++) acc[i]=0.f;
            for (int kg=0; kg<64; kg++){
                float w0=W2[(4*kg+0)*MSG_OUT+c], w1=W2[(4*kg+1)*MSG_OUT+c];
                float w2v=W2[(4*kg+2)*MSG_OUT+c], w3=W2[(4*kg+3)*MSG_OUT+c];
#pragma unroll
                for (int i=0;i<NPER;i++){
                    float4 v = ((const float4*)&sm->S0[i][0])[kg];
                    acc[i] += v.x*w0 + v.y*w1 + v.z*w2v + v.w*w3;
                }
            }
            __syncthreads();   // npos[31] written; everyone done with this layer's buffers
            float b2s = b2[c];
#pragma unroll
            for (int i=0;i<NPER;i++)
                sm->s[i][c] += acc[i]*(1.f/31.f) + b2s;
        }
        if (tid<96){
            int i = tid/3, cc = tid%3;
            sm->pos[i][cc] += sm->npos[i][cc]*(1.f/31.f);
        }
        __syncthreads();
    } // layers

    // ------------------------------------------------------------------
    // atoms = silu(s@Wh1+bh1)@Wh2+bh2 ; pos out
    // ------------------------------------------------------------------
    {
        float acc[NPER];
#pragma unroll
        for (int i=0;i<NPER;i++) acc[i]=0.f;
        for (int kg=0; kg<64; kg++){
            float w0=Wh1[(4*kg+0)*SD+c], w1=Wh1[(4*kg+1)*SD+c];
            float w2v=Wh1[(4*kg+2)*SD+c], w3=Wh1[(4*kg+3)*SD+c];
#pragma unroll
            for (int i=0;i<NPER;i++){
                float4 v = ((const float4*)&sm->s[i][0])[kg];
                acc[i] += v.x*w0 + v.y*w1 + v.z*w2v + v.w*w3;
            }
        }
        float bb = bh1[c];
#pragma unroll
        for (int i=0;i<NPER;i++) sm->P[i][c] = silu_f(acc[i]+bb);
    }
    __syncthreads();
    for (int o = tid; o < NPER*16; o += 256){
        int i = o>>4, cc = o&15;
        float a = bh2[cc];
        for (int k=0;k<SD;k++) a += sm->P[i][k]*Wh2[k*16+cc];
        outA[(nodeBase+i)*16+cc] = a;
    }
    if (tid < 96){
        int i = tid/3, cc = tid%3;
        outP[(nodeBase+i)*3+cc] = sm->pos[i][cc];
    }

    // ------------------------------------------------------------------
    // bonds: bP = s@We1s (per node); per edge: silu(bP_i+bP_j+e@We1e+d*w288+be1)@We2+be2
    // ------------------------------------------------------------------
    float* bP = &sm->hdn[0][0];          // 32 x 128
    {
        const int c128 = tid & 127;
        const int grp  = tid >> 7;       // rows grp*16 .. grp*16+15
        float acc[16];
#pragma unroll
        for (int r=0;r<16;r++) acc[r]=0.f;
        for (int kg=0; kg<64; kg++){
            float w0=We1[(4*kg+0)*128+c128], w1=We1[(4*kg+1)*128+c128];
            float w2v=We1[(4*kg+2)*128+c128], w3=We1[(4*kg+3)*128+c128];
#pragma unroll
            for (int r=0;r<16;r++){
                float4 v = ((const float4*)&sm->s[grp*16+r][0])[kg];
                acc[r] += v.x*w0 + v.y*w1 + v.z*w2v + v.w*w3;
            }
        }
#pragma unroll
        for (int r=0;r<16;r++) bP[(grp*16+r)*128 + c128] = acc[r];
    }
    float* We1e_s = &sm->W1c[0][0];      // 32 x 128
    for (int idx = tid; idx < 32*128; idx += 256)
        We1e_s[idx] = We1[(256 + (idx>>7))*128 + (idx&127)];
    __syncthreads();

    float* bh = &sm->S0[0][0];           // 16 x 128
    {
        const int c128 = tid & 127;
        const int q0   = tid >> 7;
        const float w288 = We1[288*128 + c128];
        const float bbe  = be1[c128];
        for (int p=0; p<62; p++){
            for (int idx = tid; idx < 16*ED; idx += 256){
                int q = idx>>5, k = idx&31;
                int eL = p*16 + q;
                sm->esm[q][k] = g_e[(ebase+eL)*ED + k];
            }
            if (tid < 16){
                int eL = p*16 + tid;
                int i = eL/31, jj = eL - i*31; int j = jj + (jj>=i);
                float rx=sm->pos[j][0]-sm->pos[i][0];
                float ry=sm->pos[j][1]-sm->pos[i][1];
                float rz=sm->pos[j][2]-sm->pos[i][2];
                sm->dbuf[tid] = sqrtf(fmaxf(rx*rx+ry*ry+rz*rz, 1e-6f));
            }
            __syncthreads();
#pragma unroll
            for (int qq=0; qq<8; qq++){
                int q = q0 + 2*qq;
                int eL = p*16 + q;
                int i = eL/31, jj = eL - i*31; int j = jj + (jj>=i);
                float a = bbe + bP[i*128+c128] + bP[j*128+c128] + sm->dbuf[q]*w288;
#pragma unroll
                for (int kg=0; kg<8; kg++){
                    float4 e4 = ((const float4*)&sm->esm[q][0])[kg];
                    a += e4.x*We1e_s[(4*kg+0)*128+c128] + e4.y*We1e_s[(4*kg+1)*128+c128]
                       + e4.z*We1e_s[(4*kg+2)*128+c128] + e4.w*We1e_s[(4*kg+3)*128+c128];
                }
                bh[q*128+c128] = silu_f(a);
            }
            __syncthreads();
            {   // warp wrp handles edges 2*wrp, 2*wrp+1
                for (int qq = wrp*2; qq < wrp*2+2; qq++){
                    int eL = p*16 + qq;
#pragma unroll
                    for (int b=0;b<5;b++){
                        float part = 0.f;
#pragma unroll
                        for (int m=0;m<4;m++){
                            int cc = lane + 32*m;
                            part += bh[qq*128+cc] * We2[cc*5+b];
                        }
#pragma unroll
                        for (int off=16; off>0; off>>=1)
                            part += __shfl_xor_sync(0xffffffffu, part, off);
                        if (lane==0) outB[(ebase+eL)*5+b] = part + be2[b];
                    }
                }
            }
            __syncthreads();
        }
    }
}

extern "C" void kernel_launch(void* const* d_in, const int* in_sizes, int n_in,
                              void* d_out, int out_size)
{
    const float* x    = (const float*)d_in[0];
    const float* z    = (const float*)d_in[1];
    const float* rot  = (const float*)d_in[2];
    // d_in[3] edge_index (int64) unused — structure is static block-dense
    const float* eattr= (const float*)d_in[4];
    // d_in[5] batch (int64) unused
    const float* Wam  = (const float*)d_in[6];
    const float* bam  = (const float*)d_in[7];
    const float* Wbm  = (const float*)d_in[8];
    const float* bbm  = (const float*)d_in[9];
    const float* gW1  = (const float*)d_in[10];
    const float* gb1  = (const float*)d_in[11];
    const float* gW2  = (const float*)d_in[12];
    const float* gb2  = (const float*)d_in[13];
    const float* Wh1  = (const float*)d_in[14];
    const float* bh1  = (const float*)d_in[15];
    const float* Wh2  = (const float*)d_in[16];
    const float* bh2  = (const float*)d_in[17];
    const float* We1  = (const float*)d_in[18];
    const float* be1  = (const float*)d_in[19];
    const float* We2  = (const float*)d_in[20];
    const float* be2  = (const float*)d_in[21];

    float* out  = (float*)d_out;
    float* outA = out;                                   // atoms: N x 16
    float* outB = out + (long)NNODE*16;                  // bonds: E x 5
    float* outP = out + (long)NNODE*16 + (long)ETOT*5;   // pos:   N x 3

    const size_t shmem = sizeof(SM);
    cudaFuncSetAttribute(dec_kernel, cudaFuncAttributeMaxDynamicSharedMemorySize, (int)shmem);
    dec_kernel<<<NMOL, 256, shmem>>>(x,z,rot,eattr,Wam,bam,Wbm,bbm,
                                     gW1,gb1,gW2,gb2,Wh1,bh1,Wh2,bh2,
                                     We1,be1,We2,be2,outA,outB,outP);
}

// round 2
// speedup vs baseline: 1.0969x; 1.0969x over previous
#include <cuda_runtime.h>
#include <math.h>

#define NMOL 256
#define NPER 32
#define NNODE 8192
#define EPM 992                  // 32*31 edges per molecule
#define ETOT (NMOL*EPM)          // 253952
#define SD 256
#define ED 32
#define MSG_IN 546
#define MSG_OUT 353
#define NT 512                   // threads per CTA (16 warps)
#define HROWS 16                 // rows per thread-half

// e scratch: lives in global (L2-resident, 32.5MB). Sanctioned __device__ array.
__device__ float g_e[(long)ETOT*ED];

struct SM {
    float s  [NPER][SD];   // node scalar features
    float P  [NPER][SD];   // s @ W1a   (per-src part)
    float Q  [NPER][SD];   // s @ W1b + b1 (per-tgt part)
    float S0 [NPER][SD];   // sum of hdn over incoming edges (per tgt)
    float hdn[NPER][SD];   // hidden activations for current tgt j
    float W1c[ED][SD];     // e-part of W1 (staged per layer)
    float esm[NPER][ED];   // e rows for current tgt j
    float pos [NPER][3];
    float npos[NPER][3];   // pos delta accumulator
    float dbuf[NPER];
    float abuf[NPER];
    float rnb [NPER][3];
    float w2p [SD];
    float pdpart[16][3];
    float s0p[2][SD];      // per-half partial sums of hdn (for S0)
};

__device__ __forceinline__ float silu_f(float v){
    return v * (1.0f / (1.0f + __expf(-v)));
}

__global__ void __launch_bounds__(NT,1) dec_kernel(
    const float* __restrict__ x,   const float* __restrict__ z,
    const float* __restrict__ rot, const float* __restrict__ eattr,
    const float* __restrict__ Wam, const float* __restrict__ bam,
    const float* __restrict__ Wbm, const float* __restrict__ bbm,
    const float* __restrict__ gW1, const float* __restrict__ gb1,
    const float* __restrict__ gW2, const float* __restrict__ gb2,
    const float* __restrict__ Wh1, const float* __restrict__ bh1,
    const float* __restrict__ Wh2, const float* __restrict__ bh2,
    const float* __restrict__ We1, const float* __restrict__ be1,
    const float* __restrict__ We2, const float* __restrict__ be2,
    float* __restrict__ outA, float* __restrict__ outB, float* __restrict__ outP)
{
    extern __shared__ float smraw[];
    SM* sm = (SM*)smraw;
    const int tid  = threadIdx.x;
    const int lane = tid & 31;
    const int wrp  = tid >> 5;        // 0..15
    const int mol  = blockIdx.x;
    const int nodeBase = mol * NPER;
    const long ebase   = (long)mol * EPM;
    const int c  = tid & 255;         // column owned by this thread (0..255)
    const int hh = tid >> 8;          // row-half (0/1)
    const int r0 = hh * HROWS;        // first row of this thread's half

    // ------------------------------------------------------------------
    // Embed: h = [x,z] @ Wam + bam ; s = h[:,:256]; pos = rot @ h[:,256:259]
    // ------------------------------------------------------------------
    {
        float* xz = &sm->hdn[0][0];                 // reuse: 32*80 floats
        for (int idx = tid; idx < NPER*80; idx += NT){
            int i = idx / 80, k = idx % 80;
            xz[idx] = (k < 16) ? x[(nodeBase+i)*16 + k]
                               : z[(nodeBase+i)*64 + (k-16)];
        }
        __syncthreads();
        float acc[HROWS];
#pragma unroll
        for (int r=0;r<HROWS;r++) acc[r]=0.f;
        for (int kg=0; kg<20; kg++){
            float w0=Wam[(4*kg+0)*259+c], w1=Wam[(4*kg+1)*259+c];
            float w2v=Wam[(4*kg+2)*259+c], w3=Wam[(4*kg+3)*259+c];
#pragma unroll
            for (int r=0;r<HROWS;r++){
                float4 v = ((const float4*)xz)[(r0+r)*20+kg];
                acc[r] += v.x*w0 + v.y*w1 + v.z*w2v + v.w*w3;
            }
        }
        float b = bam[c];
#pragma unroll
        for (int r=0;r<HROWS;r++) sm->s[r0+r][c] = acc[r] + b;
        if (tid < 96){                                // pos3 into npos (tmp)
            int i = tid/3, cc = tid%3;
            float a = bam[256+cc];
            for (int k=0;k<80;k++) a += xz[i*80+k]*Wam[k*259+256+cc];
            sm->npos[i][cc] = a;
        }
        __syncthreads();
        if (tid < 96){
            int i = tid/3, cc = tid%3;
            float p = 0.f;
#pragma unroll
            for (int q=0;q<3;q++) p += rot[mol*9 + cc*3 + q]*sm->npos[i][q];
            sm->pos[i][cc] = p;
        }
    }

    // ------------------------------------------------------------------
    // e init: e = edge_attr @ Wbm + bbm   (into global scratch)
    // ------------------------------------------------------------------
    for (int idx = tid; idx < EPM*ED; idx += NT){
        int eL = idx >> 5, k = idx & 31;
        const float* ea = &eattr[(ebase+eL)*5];
        float a = bbm[k];
#pragma unroll
        for (int q=0;q<5;q++) a += ea[q]*Wbm[q*ED+k];
        g_e[(ebase+eL)*ED + k] = a;
    }
    __syncthreads();

    // ------------------------------------------------------------------
    // 5 message-passing layers
    // ------------------------------------------------------------------
    for (int l=0; l<5; l++){
        const float* W1 = gW1 + (long)l*MSG_IN*SD;
        const float* b1 = gb1 + l*SD;
        const float* W2 = gW2 + (long)l*SD*MSG_OUT;
        const float* b2 = gb2 + l*MSG_OUT;

        // stage W1c (rows 512..543), w2p (col 320 of W2), zero npos
        for (int idx = tid; idx < ED*SD; idx += NT)
            sm->W1c[idx>>8][idx&255] = W1[512*SD + idx];
        if (tid < 256) sm->w2p[tid] = W2[tid*MSG_OUT + 320];
        if (tid < 96) sm->npos[tid/3][tid%3] = 0.f;
        __syncthreads();

        // P = s@W1a ; Q = s@W1b + b1   (thread: column c, 16 rows)
        {
            float accP[HROWS], accQ[HROWS];
#pragma unroll
            for (int r=0;r<HROWS;r++){ accP[r]=0.f; accQ[r]=0.f; }
            for (int kg=0; kg<64; kg++){
                float wa0=W1[(4*kg+0)*SD+c], wa1=W1[(4*kg+1)*SD+c];
                float wa2=W1[(4*kg+2)*SD+c], wa3=W1[(4*kg+3)*SD+c];
                float wb0=W1[(256+4*kg+0)*SD+c], wb1=W1[(256+4*kg+1)*SD+c];
                float wb2=W1[(256+4*kg+2)*SD+c], wb3=W1[(256+4*kg+3)*SD+c];
#pragma unroll
                for (int r=0;r<HROWS;r++){
                    float4 v = ((const float4*)&sm->s[r0+r][0])[kg];
                    accP[r] += v.x*wa0 + v.y*wa1 + v.z*wa2 + v.w*wa3;
                    accQ[r] += v.x*wb0 + v.y*wb1 + v.z*wb2 + v.w*wb3;
                }
            }
            float bb = b1[c];
#pragma unroll
            for (int r=0;r<HROWS;r++){ sm->P[r0+r][c]=accP[r]; sm->Q[r0+r][c]=accQ[r]+bb; }
        }
        __syncthreads();

        const float w1d = W1[544*SD+c];
        const float w1e = W1[545*SD+c];
        const float b2p = __ldg(&b2[320]);

        for (int j=0; j<NPER; j++){
            // [A] fold prev pdpart into npos; stage e rows + geometry
            if (j>0 && tid<3){
                float sum=0.f;
#pragma unroll
                for (int w=0;w<16;w++) sum += sm->pdpart[w][tid];
                sm->npos[j-1][tid] += sum;
            }
            for (int idx = tid; idx < NPER*ED; idx += NT){
                int i = idx>>5, k = idx&31;
                float v = 0.f;
                if (i != j){
                    int eL = i*31 + j - (j>i);
                    v = g_e[(ebase+eL)*ED + k];
                }
                sm->esm[i][k] = v;
            }
            if (tid < NPER){
                int i = tid;
                float pix=sm->pos[i][0], piy=sm->pos[i][1], piz=sm->pos[i][2];
                float pjx=sm->pos[j][0], pjy=sm->pos[j][1], pjz=sm->pos[j][2];
                float rx=pjx-pix, ry=pjy-piy, rz=pjz-piz;
                float rr = rx*rx + ry*ry + rz*rz;
                float d  = sqrtf(fmaxf(rr, 1e-6f));
                float inv = 1.f/(1.f + d);
                sm->dbuf[i] = d;
                sm->abuf[i] = pix*pjx + piy*pjy + piz*pjz;
                if (i == j){ rx=0.f; ry=0.f; rz=0.f; }
                sm->rnb[i][0]=rx*inv; sm->rnb[i][1]=ry*inv; sm->rnb[i][2]=rz*inv;
            }
            __syncthreads();

            // [B] hdn = silu(P[i]+Q[j]+e@W1c+d*w1d+a*w1e) ; partial row-sum
            {
                float acc[HROWS];
                float qj = sm->Q[j][c];
#pragma unroll
                for (int r=0;r<HROWS;r++){
                    int i = r0 + r;
                    acc[r] = sm->P[i][c] + qj + sm->dbuf[i]*w1d + sm->abuf[i]*w1e;
                }
#pragma unroll
                for (int kg=0; kg<8; kg++){
                    float w0=sm->W1c[4*kg+0][c], w1=sm->W1c[4*kg+1][c];
                    float w2v=sm->W1c[4*kg+2][c], w3=sm->W1c[4*kg+3][c];
#pragma unroll
                    for (int r=0;r<HROWS;r++){
                        float4 e4 = ((const float4*)&sm->esm[r0+r][0])[kg];
                        acc[r] += e4.x*w0 + e4.y*w1 + e4.z*w2v + e4.w*w3;
                    }
                }
                float s0 = 0.f;
#pragma unroll
                for (int r=0;r<HROWS;r++){
                    int i = r0 + r;
                    float h = (i==j) ? 0.f : silu_f(acc[r]);
                    sm->hdn[i][c] = h;
                    s0 += h;
                }
                sm->s0p[hh][c] = s0;
            }
            __syncthreads();

            // [C0] combine partial sums into S0[j]
            if (tid < 256) sm->S0[j][tid] = sm->s0p[0][tid] + sm->s0p[1][tid];

            // [C1] pos scalars: t_e = hdn.w2p ; pdpart = sum rn*(t+b2p)
            {
                float pdx=0.f, pdy=0.f, pdz=0.f;
#pragma unroll
                for (int r=0;r<2;r++){
                    int i = wrp + 16*r;
                    float part = 0.f;
#pragma unroll
                    for (int m=0;m<8;m++)
                        part += sm->hdn[i][lane+32*m] * sm->w2p[lane+32*m];
#pragma unroll
                    for (int off=16; off>0; off>>=1)
                        part += __shfl_xor_sync(0xffffffffu, part, off);
                    if (lane==0){
                        float t = part + b2p;
                        pdx += sm->rnb[i][0]*t;
                        pdy += sm->rnb[i][1]*t;
                        pdz += sm->rnb[i][2]*t;
                    }
                }
                if (lane==0){ sm->pdpart[wrp][0]=pdx; sm->pdpart[wrp][1]=pdy; sm->pdpart[wrp][2]=pdz; }
            }
            // [C2] e update: e += hdn @ W2e + b2e  (warp: k=lane, 2 rows each)
            {
                const int k = lane, g = wrp;
                const int i0=g, i1=g+16;
                float bk = __ldg(&b2[321+k]);
                float a0=bk, a1=bk;
#pragma unroll 8
                for (int c4=0; c4<64; c4++){
                    float4 h0 = ((const float4*)&sm->hdn[i0][0])[c4];
                    float4 h1 = ((const float4*)&sm->hdn[i1][0])[c4];
                    float w0 = W2[(4*c4+0)*MSG_OUT + 321 + k];
                    float w1 = W2[(4*c4+1)*MSG_OUT + 321 + k];
                    float w2v= W2[(4*c4+2)*MSG_OUT + 321 + k];
                    float w3 = W2[(4*c4+3)*MSG_OUT + 321 + k];
                    a0 += h0.x*w0 + h0.y*w1 + h0.z*w2v + h0.w*w3;
                    a1 += h1.x*w0 + h1.y*w1 + h1.z*w2v + h1.w*w3;
                }
                float accs[2] = {a0,a1};
#pragma unroll
                for (int r=0;r<2;r++){
                    int i = g + 16*r;
                    if (i != j){
                        int eL = i*31 + j - (j>i);
                        g_e[(ebase+eL)*ED + k] = accs[r] + sm->esm[i][k];
                    }
                }
            }
            __syncthreads();
        } // j

        if (tid<3){
            float sum=0.f;
#pragma unroll
            for (int w=0;w<16;w++) sum += sm->pdpart[w][tid];
            sm->npos[31][tid] += sum;
        }
        // s += (S0 @ W2s)/31 + b2s
        {
            float acc[HROWS];
#pragma unroll
            for (int r=0;r<HROWS;r++) acc[r]=0.f;
            for (int kg=0; kg<64; kg++){
                float w0=W2[(4*kg+0)*MSG_OUT+c], w1=W2[(4*kg+1)*MSG_OUT+c];
                float w2v=W2[(4*kg+2)*MSG_OUT+c], w3=W2[(4*kg+3)*MSG_OUT+c];
#pragma unroll
                for (int r=0;r<HROWS;r++){
                    float4 v = ((const float4*)&sm->S0[r0+r][0])[kg];
                    acc[r] += v.x*w0 + v.y*w1 + v.z*w2v + v.w*w3;
                }
            }
            __syncthreads();   // npos[31] written; everyone done with this layer's buffers
            float b2s = b2[c];
#pragma unroll
            for (int r=0;r<HROWS;r++)
                sm->s[r0+r][c] += acc[r]*(1.f/31.f) + b2s;
        }
        if (tid<96){
            int i = tid/3, cc = tid%3;
            sm->pos[i][cc] += sm->npos[i][cc]*(1.f/31.f);
        }
        __syncthreads();
    } // layers

    // ------------------------------------------------------------------
    // atoms = silu(s@Wh1+bh1)@Wh2+bh2 ; pos out
    // ------------------------------------------------------------------
    {
        float acc[HROWS];
#pragma unroll
        for (int r=0;r<HROWS;r++) acc[r]=0.f;
        for (int kg=0; kg<64; kg++){
            float w0=Wh1[(4*kg+0)*SD+c], w1=Wh1[(4*kg+1)*SD+c];
            float w2v=Wh1[(4*kg+2)*SD+c], w3=Wh1[(4*kg+3)*SD+c];
#pragma unroll
            for (int r=0;r<HROWS;r++){
                float4 v = ((const float4*)&sm->s[r0+r][0])[kg];
                acc[r] += v.x*w0 + v.y*w1 + v.z*w2v + v.w*w3;
            }
        }
        float bb = bh1[c];
#pragma unroll
        for (int r=0;r<HROWS;r++) sm->P[r0+r][c] = silu_f(acc[r]+bb);
    }
    __syncthreads();
    for (int o = tid; o < NPER*16; o += NT){
        int i = o>>4, cc = o&15;
        float a = bh2[cc];
        for (int k=0;k<SD;k++) a += sm->P[i][k]*Wh2[k*16+cc];
        outA[(nodeBase+i)*16+cc] = a;
    }
    if (tid < 96){
        int i = tid/3, cc = tid%3;
        outP[(nodeBase+i)*3+cc] = sm->pos[i][cc];
    }

    // ------------------------------------------------------------------
    // bonds: bP = s@We1s (per node); per edge: silu(bP_i+bP_j+e@We1e+d*w288+be1)@We2+be2
    // ------------------------------------------------------------------
    float* bP = &sm->hdn[0][0];          // 32 x 128
    {
        const int c128 = tid & 127;
        const int grp  = tid >> 7;       // 0..3, rows grp*8 .. grp*8+7
        float acc[8];
#pragma unroll
        for (int r=0;r<8;r++) acc[r]=0.f;
        for (int kg=0; kg<64; kg++){
            float w0=We1[(4*kg+0)*128+c128], w1=We1[(4*kg+1)*128+c128];
            float w2v=We1[(4*kg+2)*128+c128], w3=We1[(4*kg+3)*128+c128];
#pragma unroll
            for (int r=0;r<8;r++){
                float4 v = ((const float4*)&sm->s[grp*8+r][0])[kg];
                acc[r] += v.x*w0 + v.y*w1 + v.z*w2v + v.w*w3;
            }
        }
#pragma unroll
        for (int r=0;r<8;r++) bP[(grp*8+r)*128 + c128] = acc[r];
    }
    float* We1e_s = &sm->W1c[0][0];      // 32 x 128
    for (int idx = tid; idx < 32*128; idx += NT)
        We1e_s[idx] = We1[(256 + (idx>>7))*128 + (idx&127)];
    __syncthreads();

    float* bh = &sm->S0[0][0];           // 16 x 128
    {
        const int c128 = tid & 127;
        const int grp  = tid >> 7;       // 0..3
        const float w288 = We1[288*128 + c128];
        const float bbe  = be1[c128];
        for (int p=0; p<62; p++){
            for (int idx = tid; idx < 16*ED; idx += NT){
                int q = idx>>5, k = idx&31;
                int eL = p*16 + q;
                sm->esm[q][k] = g_e[(ebase+eL)*ED + k];
            }
            if (tid < 16){
                int eL = p*16 + tid;
                int i = eL/31, jj = eL - i*31; int j = jj + (jj>=i);
                float rx=sm->pos[j][0]-sm->pos[i][0];
                float ry=sm->pos[j][1]-sm->pos[i][1];
                float rz=sm->pos[j][2]-sm->pos[i][2];
                sm->dbuf[tid] = sqrtf(fmaxf(rx*rx+ry*ry+rz*rz, 1e-6f));
            }
            __syncthreads();
#pragma unroll
            for (int qq=0; qq<4; qq++){
                int q = grp*4 + qq;
                int eL = p*16 + q;
                int i = eL/31, jj = eL - i*31; int j = jj + (jj>=i);
                float a = bbe + bP[i*128+c128] + bP[j*128+c128] + sm->dbuf[q]*w288;
#pragma unroll
                for (int kg=0; kg<8; kg++){
                    float4 e4 = ((const float4*)&sm->esm[q][0])[kg];
                    a += e4.x*We1e_s[(4*kg+0)*128+c128] + e4.y*We1e_s[(4*kg+1)*128+c128]
                       + e4.z*We1e_s[(4*kg+2)*128+c128] + e4.w*We1e_s[(4*kg+3)*128+c128];
                }
                bh[q*128+c128] = silu_f(a);
            }
            __syncthreads();
            {   // warp wrp handles edge wrp of this chunk
                int qq = wrp;
                int eL = p*16 + qq;
#pragma unroll
                for (int b=0;b<5;b++){
                    float part = 0.f;
#pragma unroll
                    for (int m=0;m<4;m++){
                        int cc = lane + 32*m;
                        part += bh[qq*128+cc] * We2[cc*5+b];
                    }
#pragma unroll
                    for (int off=16; off>0; off>>=1)
                        part += __shfl_xor_sync(0xffffffffu, part, off);
                    if (lane==0) outB[(ebase+eL)*5+b] = part + be2[b];
                }
            }
            __syncthreads();
        }
    }
}

extern "C" void kernel_launch(void* const* d_in, const int* in_sizes, int n_in,
                              void* d_out, int out_size)
{
    const float* x    = (const float*)d_in[0];
    const float* z    = (const float*)d_in[1];
    const float* rot  = (const float*)d_in[2];
    // d_in[3] edge_index (int64) unused — structure is static block-dense
    const float* eattr= (const float*)d_in[4];
    // d_in[5] batch (int64) unused
    const float* Wam  = (const float*)d_in[6];
    const float* bam  = (const float*)d_in[7];
    const float* Wbm  = (const float*)d_in[8];
    const float* bbm  = (const float*)d_in[9];
    const float* gW1  = (const float*)d_in[10];
    const float* gb1  = (const float*)d_in[11];
    const float* gW2  = (const float*)d_in[12];
    const float* gb2  = (const float*)d_in[13];
    const float* Wh1  = (const float*)d_in[14];
    const float* bh1  = (const float*)d_in[15];
    const float* Wh2  = (const float*)d_in[16];
    const float* bh2  = (const float*)d_in[17];
    const float* We1  = (const float*)d_in[18];
    const float* be1  = (const float*)d_in[19];
    const float* We2  = (const float*)d_in[20];
    const float* be2  = (const float*)d_in[21];

    float* out  = (float*)d_out;
    float* outA = out;                                   // atoms: N x 16
    float* outB = out + (long)NNODE*16;                  // bonds: E x 5
    float* outP = out + (long)NNODE*16 + (long)ETOT*5;   // pos:   N x 3

    const size_t shmem = sizeof(SM);
    cudaFuncSetAttribute(dec_kernel, cudaFuncAttributeMaxDynamicSharedMemorySize, (int)shmem);
    dec_kernel<<<NMOL, NT, shmem>>>(x,z,rot,eattr,Wam,bam,Wbm,bbm,
                                    gW1,gb1,gW2,gb2,Wh1,bh1,Wh2,bh2,
                                    We1,be1,We2,be2,outA,outB,outP);
}

// round 3
// speedup vs baseline: 1.1448x; 1.0437x over previous
#include <cuda_runtime.h>
#include <math.h>

#define NMOL 256
#define NPER 32
#define NNODE 8192
#define EPM 992                  // 32*31 edges per molecule
#define ETOT (NMOL*EPM)          // 253952
#define SD 256
#define ED 32
#define MSG_IN 546
#define MSG_OUT 353
#define NT 512                   // threads per CTA (16 warps)
#define HROWS 16                 // rows per thread-half (for 256-col sections)

typedef unsigned long long u64;

// e scratch: lives in global (L2-resident, 32.5MB). Sanctioned __device__ array.
__device__ float g_e[(long)ETOT*ED];
// transposed/packed W2e weights: layout [l][c4][k][4]  (l<5, c4<64, k<32, 4 cols)
__device__ __align__(16) float g_w2t[5*64*32*4];

struct SM {
    float s  [NPER][SD];   // node scalar features
    float P  [NPER][SD];   // s @ W1a   (per-src part)
    float Q  [NPER][SD];   // s @ W1b + b1 (per-tgt part)
    float S0 [NPER][SD];   // sum of hdn over incoming edges (per tgt)
    float hdn[NPER][SD];   // hidden activations for current tgt j
    float W1c[ED][SD];     // e-part of W1 (staged per layer)
    float esm2[NPER][2*ED];// e rows for current tgt j, DUPLICATED pairs {v,v}
    float pos [NPER][3];
    float npos[NPER][3];   // pos delta accumulator
    float dbuf[NPER];
    float abuf[NPER];
    float rnb [NPER][3];
    float w2p [SD];
    float pdpart[16][3];
    float s0q[4][SD];      // per-quarter partial sums of hdn (for S0)
};

__device__ __forceinline__ float silu_f(float v){
    return v * (1.0f / (1.0f + __expf(-v)));
}
__device__ __forceinline__ u64 pack2(float x, float y){
    u64 r; asm("mov.b64 %0, {%1, %2};" : "=l"(r) : "f"(x), "f"(y)); return r;
}
__device__ __forceinline__ void unpack2(u64 v, float& x, float& y){
    asm("mov.b64 {%0, %1}, %2;" : "=f"(x), "=f"(y) : "l"(v));
}
__device__ __forceinline__ u64 fma2(u64 a, u64 b, u64 c){
    u64 d; asm("fma.rn.f32x2 %0, %1, %2, %3;" : "=l"(d) : "l"(a), "l"(b), "l"(c)); return d;
}
__device__ __forceinline__ u64 add2(u64 a, u64 b){
    u64 d; asm("add.rn.f32x2 %0, %1, %2;" : "=l"(d) : "l"(a), "l"(b)); return d;
}
__device__ __forceinline__ u64 dup2(float x){ return pack2(x,x); }

// prep: g_w2t[l*8192 + c4*128 + k*4 + cc] = W2e[4*c4+cc][k] = gW2[(l*256+4*c4+cc)*353 + 321 + k]
__global__ void prep_kernel(const float* __restrict__ gW2){
    int idx = blockIdx.x*256 + threadIdx.x;
    if (idx >= 5*8192) return;
    int l = idx >> 13; int rem = idx & 8191;
    int c4 = rem >> 7; int rem2 = rem & 127;
    int k = rem2 >> 2; int cc = rem2 & 3;
    g_w2t[idx] = gW2[((long)l*256 + 4*c4 + cc)*MSG_OUT + 321 + k];
}

__global__ void __launch_bounds__(NT,1) dec_kernel(
    const float* __restrict__ x,   const float* __restrict__ z,
    const float* __restrict__ rot, const float* __restrict__ eattr,
    const float* __restrict__ Wam, const float* __restrict__ bam,
    const float* __restrict__ Wbm, const float* __restrict__ bbm,
    const float* __restrict__ gW1, const float* __restrict__ gb1,
    const float* __restrict__ gW2, const float* __restrict__ gb2,
    const float* __restrict__ Wh1, const float* __restrict__ bh1,
    const float* __restrict__ Wh2, const float* __restrict__ bh2,
    const float* __restrict__ We1, const float* __restrict__ be1,
    const float* __restrict__ We2, const float* __restrict__ be2,
    float* __restrict__ outA, float* __restrict__ outB, float* __restrict__ outP)
{
    extern __shared__ float smraw[];
    SM* sm = (SM*)smraw;
    const int tid  = threadIdx.x;
    const int lane = tid & 31;
    const int wrp  = tid >> 5;        // 0..15
    const int mol  = blockIdx.x;
    const int nodeBase = mol * NPER;
    const long ebase   = (long)mol * EPM;
    const int c  = tid & 255;         // column (0..255) for 256-col sections
    const int hh = tid >> 8;          // row-half (0/1)
    const int r0 = hh * HROWS;
    const int p  = tid & 127;         // col-pair index (cols 2p, 2p+1) for [B]
    const int q4 = tid >> 7;          // row-quarter (0..3) for [B]
    const int rq = q4 * 8;            // first row of this quarter

    // ------------------------------------------------------------------
    // Embed: h = [x,z] @ Wam + bam ; s = h[:,:256]; pos = rot @ h[:,256:259]
    // ------------------------------------------------------------------
    {
        float* xz = &sm->hdn[0][0];                 // reuse: 32*80 floats
        for (int idx = tid; idx < NPER*80; idx += NT){
            int i = idx / 80, k = idx % 80;
            xz[idx] = (k < 16) ? x[(nodeBase+i)*16 + k]
                               : z[(nodeBase+i)*64 + (k-16)];
        }
        __syncthreads();
        float acc[HROWS];
#pragma unroll
        for (int r=0;r<HROWS;r++) acc[r]=0.f;
        for (int kg=0; kg<20; kg++){
            float w0=Wam[(4*kg+0)*259+c], w1=Wam[(4*kg+1)*259+c];
            float w2v=Wam[(4*kg+2)*259+c], w3=Wam[(4*kg+3)*259+c];
#pragma unroll
            for (int r=0;r<HROWS;r++){
                float4 v = ((const float4*)xz)[(r0+r)*20+kg];
                acc[r] += v.x*w0 + v.y*w1 + v.z*w2v + v.w*w3;
            }
        }
        float b = bam[c];
#pragma unroll
        for (int r=0;r<HROWS;r++) sm->s[r0+r][c] = acc[r] + b;
        if (tid < 96){                                // pos3 into npos (tmp)
            int i = tid/3, cc = tid%3;
            float a = bam[256+cc];
            for (int k=0;k<80;k++) a += xz[i*80+k]*Wam[k*259+256+cc];
            sm->npos[i][cc] = a;
        }
        __syncthreads();
        if (tid < 96){
            int i = tid/3, cc = tid%3;
            float pv = 0.f;
#pragma unroll
            for (int q=0;q<3;q++) pv += rot[mol*9 + cc*3 + q]*sm->npos[i][q];
            sm->pos[i][cc] = pv;
        }
    }

    // ------------------------------------------------------------------
    // e init: e = edge_attr @ Wbm + bbm   (into global scratch)
    // ------------------------------------------------------------------
    for (int idx = tid; idx < EPM*ED; idx += NT){
        int eL = idx >> 5, k = idx & 31;
        const float* ea = &eattr[(ebase+eL)*5];
        float a = bbm[k];
#pragma unroll
        for (int q=0;q<5;q++) a += ea[q]*Wbm[q*ED+k];
        g_e[(ebase+eL)*ED + k] = a;
    }
    __syncthreads();

    // ------------------------------------------------------------------
    // 5 message-passing layers
    // ------------------------------------------------------------------
    for (int l=0; l<5; l++){
        const float* W1 = gW1 + (long)l*MSG_IN*SD;
        const float* b1 = gb1 + l*SD;
        const float* W2 = gW2 + (long)l*SD*MSG_OUT;
        const float* b2 = gb2 + l*MSG_OUT;

        // stage W1c (rows 512..543), w2p (col 320 of W2), zero npos
        for (int idx = tid; idx < ED*SD; idx += NT)
            sm->W1c[idx>>8][idx&255] = W1[512*SD + idx];
        if (tid < 256) sm->w2p[tid] = W2[tid*MSG_OUT + 320];
        if (tid < 96) sm->npos[tid/3][tid%3] = 0.f;
        __syncthreads();

        // P = s@W1a ; Q = s@W1b + b1   (thread: column c, 16 rows)
        {
            float accP[HROWS], accQ[HROWS];
#pragma unroll
            for (int r=0;r<HROWS;r++){ accP[r]=0.f; accQ[r]=0.f; }
            for (int kg=0; kg<64; kg++){
                float wa0=W1[(4*kg+0)*SD+c], wa1=W1[(4*kg+1)*SD+c];
                float wa2=W1[(4*kg+2)*SD+c], wa3=W1[(4*kg+3)*SD+c];
                float wb0=W1[(256+4*kg+0)*SD+c], wb1=W1[(256+4*kg+1)*SD+c];
                float wb2=W1[(256+4*kg+2)*SD+c], wb3=W1[(256+4*kg+3)*SD+c];
#pragma unroll
                for (int r=0;r<HROWS;r++){
                    float4 v = ((const float4*)&sm->s[r0+r][0])[kg];
                    accP[r] += v.x*wa0 + v.y*wa1 + v.z*wa2 + v.w*wa3;
                    accQ[r] += v.x*wb0 + v.y*wb1 + v.z*wb2 + v.w*wb3;
                }
            }
            float bb = b1[c];
#pragma unroll
            for (int r=0;r<HROWS;r++){ sm->P[r0+r][c]=accP[r]; sm->Q[r0+r][c]=accQ[r]+bb; }
        }
        __syncthreads();

        // per-layer packed constants for [B] (col-pair 2p,2p+1)
        const u64 w1d2 = *(const u64*)&W1[544*SD + 2*p];
        const u64 w1e2 = *(const u64*)&W1[545*SD + 2*p];
        const float b2p = __ldg(&b2[320]);
        const float* wt = g_w2t + l*8192 + lane*4;    // for [C2]

        for (int j=0; j<NPER; j++){
            // [A] fold prev pdpart into npos; stage e rows (duplicated) + geometry
            if (j>0 && tid<3){
                float sum=0.f;
#pragma unroll
                for (int w=0;w<16;w++) sum += sm->pdpart[w][tid];
                sm->npos[j-1][tid] += sum;
            }
            for (int idx = tid; idx < NPER*ED; idx += NT){
                int i = idx>>5, k = idx&31;
                float v = 0.f;
                if (i != j){
                    int eL = i*31 + j - (j>i);
                    v = g_e[(ebase+eL)*ED + k];
                }
                *(float2*)&sm->esm2[i][2*k] = make_float2(v, v);
            }
            if (tid < NPER){
                int i = tid;
                float pix=sm->pos[i][0], piy=sm->pos[i][1], piz=sm->pos[i][2];
                float pjx=sm->pos[j][0], pjy=sm->pos[j][1], pjz=sm->pos[j][2];
                float rx=pjx-pix, ry=pjy-piy, rz=pjz-piz;
                float rr = rx*rx + ry*ry + rz*rz;
                float d  = sqrtf(fmaxf(rr, 1e-6f));
                float inv = 1.f/(1.f + d);
                sm->dbuf[i] = d;
                sm->abuf[i] = pix*pjx + piy*pjy + piz*pjz;
                if (i == j){ rx=0.f; ry=0.f; rz=0.f; }
                sm->rnb[i][0]=rx*inv; sm->rnb[i][1]=ry*inv; sm->rnb[i][2]=rz*inv;
            }
            __syncthreads();

            // [B] hdn = silu(P[i]+Q[j]+e@W1c+d*w1d+a*w1e), packed f32x2
            //     thread: col-pair (2p,2p+1), rows rq..rq+7
            {
                u64 acc[8];
                const u64 Q2 = *(const u64*)&sm->Q[j][2*p];
#pragma unroll
                for (int r=0;r<8;r++){
                    int i = rq + r;
                    u64 t = add2(*(const u64*)&sm->P[i][2*p], Q2);
                    t = fma2(dup2(sm->dbuf[i]), w1d2, t);
                    t = fma2(dup2(sm->abuf[i]), w1e2, t);
                    acc[r] = t;
                }
#pragma unroll 4
                for (int k2=0;k2<16;k2++){
                    u64 w0 = *(const u64*)&sm->W1c[2*k2  ][2*p];
                    u64 w1 = *(const u64*)&sm->W1c[2*k2+1][2*p];
#pragma unroll
                    for (int r=0;r<8;r++){
                        const ulonglong2 e2 = *(const ulonglong2*)&sm->esm2[rq+r][4*k2];
                        acc[r] = fma2(e2.x, w0, acc[r]);
                        acc[r] = fma2(e2.y, w1, acc[r]);
                    }
                }
                float s0x=0.f, s0y=0.f;
#pragma unroll
                for (int r=0;r<8;r++){
                    int i = rq + r;
                    float hx,hy; unpack2(acc[r],hx,hy);
                    hx = silu_f(hx); hy = silu_f(hy);
                    if (i==j){ hx=0.f; hy=0.f; }
                    *(float2*)&sm->hdn[i][2*p] = make_float2(hx,hy);
                    s0x += hx; s0y += hy;
                }
                *(float2*)&sm->s0q[q4][2*p] = make_float2(s0x,s0y);
            }
            __syncthreads();

            // [C0] combine partial sums into S0[j]
            if (tid < 256)
                sm->S0[j][tid] = sm->s0q[0][tid] + sm->s0q[1][tid]
                               + sm->s0q[2][tid] + sm->s0q[3][tid];

            // [C1] pos scalars: t_e = hdn.w2p ; pdpart = sum rn*(t+b2p)
            {
                float pdx=0.f, pdy=0.f, pdz=0.f;
#pragma unroll
                for (int r=0;r<2;r++){
                    int i = wrp + 16*r;
                    float part = 0.f;
#pragma unroll
                    for (int m=0;m<8;m++)
                        part += sm->hdn[i][lane+32*m] * sm->w2p[lane+32*m];
#pragma unroll
                    for (int off=16; off>0; off>>=1)
                        part += __shfl_xor_sync(0xffffffffu, part, off);
                    if (lane==0){
                        float t = part + b2p;
                        pdx += sm->rnb[i][0]*t;
                        pdy += sm->rnb[i][1]*t;
                        pdz += sm->rnb[i][2]*t;
                    }
                }
                if (lane==0){ sm->pdpart[wrp][0]=pdx; sm->pdpart[wrp][1]=pdy; sm->pdpart[wrp][2]=pdz; }
            }
            // [C2] e update: e += hdn @ W2e + b2e, packed f32x2, coalesced weights
            //      warp wrp: k=lane, rows {wrp, wrp+16}
            {
                const int k = lane;
                const int i0=wrp, i1=wrp+16;
                u64 a0 = 0ULL, a1 = 0ULL;
#pragma unroll 8
                for (int c4=0;c4<64;c4++){
                    ulonglong2 h0 = *(const ulonglong2*)&sm->hdn[i0][4*c4];
                    ulonglong2 h1 = *(const ulonglong2*)&sm->hdn[i1][4*c4];
                    ulonglong2 ww = *(const ulonglong2*)&wt[c4*128];
                    a0 = fma2(h0.x, ww.x, a0); a0 = fma2(h0.y, ww.y, a0);
                    a1 = fma2(h1.x, ww.x, a1); a1 = fma2(h1.y, ww.y, a1);
                }
                float bk = __ldg(&b2[321+k]);
                float x0,y0,x1,y1;
                unpack2(a0,x0,y0); unpack2(a1,x1,y1);
                float v0 = x0+y0+bk, v1 = x1+y1+bk;
                if (i0 != j){
                    int eL = i0*31 + j - (j>i0);
                    g_e[(ebase+eL)*ED + k] = v0 + sm->esm2[i0][2*k];
                }
                if (i1 != j){
                    int eL = i1*31 + j - (j>i1);
                    g_e[(ebase+eL)*ED + k] = v1 + sm->esm2[i1][2*k];
                }
            }
            __syncthreads();
        } // j

        if (tid<3){
            float sum=0.f;
#pragma unroll
            for (int w=0;w<16;w++) sum += sm->pdpart[w][tid];
            sm->npos[31][tid] += sum;
        }
        // s += (S0 @ W2s)/31 + b2s
        {
            float acc[HROWS];
#pragma unroll
            for (int r=0;r<HROWS;r++) acc[r]=0.f;
            for (int kg=0; kg<64; kg++){
                float w0=W2[(4*kg+0)*MSG_OUT+c], w1=W2[(4*kg+1)*MSG_OUT+c];
                float w2v=W2[(4*kg+2)*MSG_OUT+c], w3=W2[(4*kg+3)*MSG_OUT+c];
#pragma unroll
                for (int r=0;r<HROWS;r++){
                    float4 v = ((const float4*)&sm->S0[r0+r][0])[kg];
                    acc[r] += v.x*w0 + v.y*w1 + v.z*w2v + v.w*w3;
                }
            }
            __syncthreads();   // npos[31] written; everyone done with this layer's buffers
            float b2s = b2[c];
#pragma unroll
            for (int r=0;r<HROWS;r++)
                sm->s[r0+r][c] += acc[r]*(1.f/31.f) + b2s;
        }
        if (tid<96){
            int i = tid/3, cc = tid%3;
            sm->pos[i][cc] += sm->npos[i][cc]*(1.f/31.f);
        }
        __syncthreads();
    } // layers

    // ------------------------------------------------------------------
    // atoms = silu(s@Wh1+bh1)@Wh2+bh2 ; pos out
    // ------------------------------------------------------------------
    {
        float acc[HROWS];
#pragma unroll
        for (int r=0;r<HROWS;r++) acc[r]=0.f;
        for (int kg=0; kg<64; kg++){
            float w0=Wh1[(4*kg+0)*SD+c], w1=Wh1[(4*kg+1)*SD+c];
            float w2v=Wh1[(4*kg+2)*SD+c], w3=Wh1[(4*kg+3)*SD+c];
#pragma unroll
            for (int r=0;r<HROWS;r++){
                float4 v = ((const float4*)&sm->s[r0+r][0])[kg];
                acc[r] += v.x*w0 + v.y*w1 + v.z*w2v + v.w*w3;
            }
        }
        float bb = bh1[c];
#pragma unroll
        for (int r=0;r<HROWS;r++) sm->P[r0+r][c] = silu_f(acc[r]+bb);
    }
    __syncthreads();
    for (int o = tid; o < NPER*16; o += NT){
        int i = o>>4, cc = o&15;
        float a = bh2[cc];
        for (int k=0;k<SD;k++) a += sm->P[i][k]*Wh2[k*16+cc];
        outA[(nodeBase+i)*16+cc] = a;
    }
    if (tid < 96){
        int i = tid/3, cc = tid%3;
        outP[(nodeBase+i)*3+cc] = sm->pos[i][cc];
    }

    // ------------------------------------------------------------------
    // bonds: bP = s@We1s (per node); per edge: silu(bP_i+bP_j+e@We1e+d*w288+be1)@We2+be2
    // ------------------------------------------------------------------
    float* bP = &sm->hdn[0][0];          // 32 x 128
    {
        const int c128 = tid & 127;
        const int grp  = tid >> 7;       // 0..3, rows grp*8 .. grp*8+7
        float acc[8];
#pragma unroll
        for (int r=0;r<8;r++) acc[r]=0.f;
        for (int kg=0; kg<64; kg++){
            float w0=We1[(4*kg+0)*128+c128], w1=We1[(4*kg+1)*128+c128];
            float w2v=We1[(4*kg+2)*128+c128], w3=We1[(4*kg+3)*128+c128];
#pragma unroll
            for (int r=0;r<8;r++){
                float4 v = ((const float4*)&sm->s[grp*8+r][0])[kg];
                acc[r] += v.x*w0 + v.y*w1 + v.z*w2v + v.w*w3;
            }
        }
#pragma unroll
        for (int r=0;r<8;r++) bP[(grp*8+r)*128 + c128] = acc[r];
    }
    float* We1e_s = &sm->W1c[0][0];      // 32 x 128
    for (int idx = tid; idx < 32*128; idx += NT)
        We1e_s[idx] = We1[(256 + (idx>>7))*128 + (idx&127)];
    __syncthreads();

    float* bh = &sm->S0[0][0];           // 16 x 128
    float* ebuf = &sm->esm2[0][0];       // 16 x 32 scratch
    {
        const int c128 = tid & 127;
        const int grp  = tid >> 7;       // 0..3
        const float w288 = We1[288*128 + c128];
        const float bbe  = be1[c128];
        for (int pblk=0; pblk<62; pblk++){
            for (int idx = tid; idx < 16*ED; idx += NT){
                int q = idx>>5, k = idx&31;
                int eL = pblk*16 + q;
                ebuf[q*32+k] = g_e[(ebase+eL)*ED + k];
            }
            if (tid < 16){
                int eL = pblk*16 + tid;
                int i = eL/31, jj = eL - i*31; int j = jj + (jj>=i);
                float rx=sm->pos[j][0]-sm->pos[i][0];
                float ry=sm->pos[j][1]-sm->pos[i][1];
                float rz=sm->pos[j][2]-sm->pos[i][2];
                sm->dbuf[tid] = sqrtf(fmaxf(rx*rx+ry*ry+rz*rz, 1e-6f));
            }
            __syncthreads();
#pragma unroll
            for (int qq=0; qq<4; qq++){
                int q = grp*4 + qq;
                int eL = pblk*16 + q;
                int i = eL/31, jj = eL - i*31; int j = jj + (jj>=i);
                float a = bbe + bP[i*128+c128] + bP[j*128+c128] + sm->dbuf[q]*w288;
#pragma unroll
                for (int kg=0; kg<8; kg++){
                    float4 e4 = ((const float4*)&ebuf[q*32])[kg];
                    a += e4.x*We1e_s[(4*kg+0)*128+c128] + e4.y*We1e_s[(4*kg+1)*128+c128]
                       + e4.z*We1e_s[(4*kg+2)*128+c128] + e4.w*We1e_s[(4*kg+3)*128+c128];
                }
                bh[q*128+c128] = silu_f(a);
            }
            __syncthreads();
            {   // warp wrp handles edge wrp of this chunk
                int qq = wrp;
                int eL = pblk*16 + qq;
#pragma unroll
                for (int b=0;b<5;b++){
                    float part = 0.f;
#pragma unroll
                    for (int m=0;m<4;m++){
                        int cc = lane + 32*m;
                        part += bh[qq*128+cc] * We2[cc*5+b];
                    }
#pragma unroll
                    for (int off=16; off>0; off>>=1)
                        part += __shfl_xor_sync(0xffffffffu, part, off);
                    if (lane==0) outB[(ebase+eL)*5+b] = part + be2[b];
                }
            }
            __syncthreads();
        }
    }
}

extern "C" void kernel_launch(void* const* d_in, const int* in_sizes, int n_in,
                              void* d_out, int out_size)
{
    const float* x    = (const float*)d_in[0];
    const float* z    = (const float*)d_in[1];
    const float* rot  = (const float*)d_in[2];
    // d_in[3] edge_index (int64) unused — structure is static block-dense
    const float* eattr= (const float*)d_in[4];
    // d_in[5] batch (int64) unused
    const float* Wam  = (const float*)d_in[6];
    const float* bam  = (const float*)d_in[7];
    const float* Wbm  = (const float*)d_in[8];
    const float* bbm  = (const float*)d_in[9];
    const float* gW1  = (const float*)d_in[10];
    const float* gb1  = (const float*)d_in[11];
    const float* gW2  = (const float*)d_in[12];
    const float* gb2  = (const float*)d_in[13];
    const float* Wh1  = (const float*)d_in[14];
    const float* bh1  = (const float*)d_in[15];
    const float* Wh2  = (const float*)d_in[16];
    const float* bh2  = (const float*)d_in[17];
    const float* We1  = (const float*)d_in[18];
    const float* be1  = (const float*)d_in[19];
    const float* We2  = (const float*)d_in[20];
    const float* be2  = (const float*)d_in[21];

    float* out  = (float*)d_out;
    float* outA = out;                                   // atoms: N x 16
    float* outB = out + (long)NNODE*16;                  // bonds: E x 5
    float* outP = out + (long)NNODE*16 + (long)ETOT*5;   // pos:   N x 3

    prep_kernel<<<160, 256>>>(gW2);

    const size_t shmem = sizeof(SM);
    cudaFuncSetAttribute(dec_kernel, cudaFuncAttributeMaxDynamicSharedMemorySize, (int)shmem);
    dec_kernel<<<NMOL, NT, shmem>>>(x,z,rot,eattr,Wam,bam,Wbm,bbm,
                                    gW1,gb1,gW2,gb2,Wh1,bh1,Wh2,bh2,
                                    We1,be1,We2,be2,outA,outB,outP);
}

// round 4
// speedup vs baseline: 1.2171x; 1.0631x over previous
#include <cuda_runtime.h>
#include <math.h>

#define NMOL 256
#define NPER 32
#define NNODE 8192
#define EPM 992                  // 32*31 edges per molecule
#define ETOT (NMOL*EPM)          // 253952
#define SD 256
#define ED 32
#define MSG_IN 546
#define MSG_OUT 353
#define NT 512                   // threads per CTA (16 warps)
#define HROWS 16                 // rows per thread-half (for 256-col sections)

typedef unsigned long long u64;

// global scratch (sanctioned __device__ arrays)
__device__ float g_e[(long)ETOT*ED];                    // edge features (32.5MB, L2)
__device__ __align__(16) float g_w2t[5*64*32*4];        // transposed W2e  [l][c4][k][4]
__device__ __align__(16) float g_Q [(long)NMOL*NPER*SD];// per-layer Q rows
__device__ __align__(16) float g_S0[(long)NMOL*NPER*SD];// per-layer S0 rows

struct SM {
    float s  [NPER][SD];   // node scalar features            32KB
    float P  [NPER][SD];   // s @ W1a  (per-src part)         32KB
    float hdn[NPER][SD];   // hidden activations, tgt j       32KB
    float esm2[NPER][2*ED];// e rows for tgt j, duplicated     8KB
    float pos [NPER][3];
    float npos[NPER][3];
    float dbuf[NPER];
    float abuf[NPER];
    float rnb [NPER][3];
    float w2p [SD];
    float pdpart[16][3];
    float s0q[4][SD];      // per-quarter partial sums of hdn  4KB
};

__device__ __forceinline__ float silu_f(float v){
    return v * (1.0f / (1.0f + __expf(-v)));
}
__device__ __forceinline__ u64 pack2(float x, float y){
    u64 r; asm("mov.b64 %0, {%1, %2};" : "=l"(r) : "f"(x), "f"(y)); return r;
}
__device__ __forceinline__ void unpack2(u64 v, float& x, float& y){
    asm("mov.b64 {%0, %1}, %2;" : "=f"(x), "=f"(y) : "l"(v));
}
__device__ __forceinline__ u64 fma2(u64 a, u64 b, u64 c){
    u64 d; asm("fma.rn.f32x2 %0, %1, %2, %3;" : "=l"(d) : "l"(a), "l"(b), "l"(c)); return d;
}
__device__ __forceinline__ u64 add2(u64 a, u64 b){
    u64 d; asm("add.rn.f32x2 %0, %1, %2;" : "=l"(d) : "l"(a), "l"(b)); return d;
}
__device__ __forceinline__ u64 dup2(float x){ return pack2(x,x); }

// prep: g_w2t[l*8192 + c4*128 + k*4 + cc] = gW2[(l*256+4*c4+cc)*353 + 321 + k]
__global__ void prep_kernel(const float* __restrict__ gW2){
    int idx = blockIdx.x*256 + threadIdx.x;
    if (idx >= 5*8192) return;
    int l = idx >> 13; int rem = idx & 8191;
    int c4 = rem >> 7; int rem2 = rem & 127;
    int k = rem2 >> 2; int cc = rem2 & 3;
    g_w2t[idx] = gW2[((long)l*256 + 4*c4 + cc)*MSG_OUT + 321 + k];
}

__global__ void __launch_bounds__(NT,2) dec_kernel(
    const float* __restrict__ x,   const float* __restrict__ z,
    const float* __restrict__ rot, const float* __restrict__ eattr,
    const float* __restrict__ Wam, const float* __restrict__ bam,
    const float* __restrict__ Wbm, const float* __restrict__ bbm,
    const float* __restrict__ gW1, const float* __restrict__ gb1,
    const float* __restrict__ gW2, const float* __restrict__ gb2,
    const float* __restrict__ Wh1, const float* __restrict__ bh1,
    const float* __restrict__ Wh2, const float* __restrict__ bh2,
    const float* __restrict__ We1, const float* __restrict__ be1,
    const float* __restrict__ We2, const float* __restrict__ be2,
    float* __restrict__ outA, float* __restrict__ outB, float* __restrict__ outP)
{
    extern __shared__ float smraw[];
    SM* sm = (SM*)smraw;
    const int tid  = threadIdx.x;
    const int lane = tid & 31;
    const int wrp  = tid >> 5;        // 0..15
    const int mol  = blockIdx.x;
    const int nodeBase = mol * NPER;
    const long ebase   = (long)mol * EPM;
    const int c  = tid & 255;         // column (0..255) for 256-col sections
    const int hh = tid >> 8;          // row-half (0/1)
    const int r0 = hh * HROWS;
    const int p  = tid & 127;         // col-pair index (cols 2p, 2p+1) for [B]
    const int q4 = tid >> 7;          // row-quarter (0..3) for [B]
    const int rq = q4 * 8;            // first row of this quarter
    float* Qg  = g_Q  + (size_t)mol*NPER*SD;
    float* S0g = g_S0 + (size_t)mol*NPER*SD;

    // ------------------------------------------------------------------
    // Embed: h = [x,z] @ Wam + bam ; s = h[:,:256]; pos = rot @ h[:,256:259]
    // ------------------------------------------------------------------
    {
        float* xz = &sm->hdn[0][0];                 // reuse: 32*80 floats
        for (int idx = tid; idx < NPER*80; idx += NT){
            int i = idx / 80, k = idx % 80;
            xz[idx] = (k < 16) ? x[(nodeBase+i)*16 + k]
                               : z[(nodeBase+i)*64 + (k-16)];
        }
        __syncthreads();
        float acc[HROWS];
#pragma unroll
        for (int r=0;r<HROWS;r++) acc[r]=0.f;
        for (int kg=0; kg<20; kg++){
            float w0=Wam[(4*kg+0)*259+c], w1=Wam[(4*kg+1)*259+c];
            float w2v=Wam[(4*kg+2)*259+c], w3=Wam[(4*kg+3)*259+c];
#pragma unroll
            for (int r=0;r<HROWS;r++){
                float4 v = ((const float4*)xz)[(r0+r)*20+kg];
                acc[r] += v.x*w0 + v.y*w1 + v.z*w2v + v.w*w3;
            }
        }
        float b = bam[c];
#pragma unroll
        for (int r=0;r<HROWS;r++) sm->s[r0+r][c] = acc[r] + b;
        if (tid < 96){                                // pos3 into npos (tmp)
            int i = tid/3, cc = tid%3;
            float a = bam[256+cc];
            for (int k=0;k<80;k++) a += xz[i*80+k]*Wam[k*259+256+cc];
            sm->npos[i][cc] = a;
        }
        __syncthreads();
        if (tid < 96){
            int i = tid/3, cc = tid%3;
            float pv = 0.f;
#pragma unroll
            for (int q=0;q<3;q++) pv += rot[mol*9 + cc*3 + q]*sm->npos[i][q];
            sm->pos[i][cc] = pv;
        }
    }

    // ------------------------------------------------------------------
    // e init: e = edge_attr @ Wbm + bbm   (into global scratch)
    // ------------------------------------------------------------------
    for (int idx = tid; idx < EPM*ED; idx += NT){
        int eL = idx >> 5, k = idx & 31;
        const float* ea = &eattr[(ebase+eL)*5];
        float a = bbm[k];
#pragma unroll
        for (int q=0;q<5;q++) a += ea[q]*Wbm[q*ED+k];
        g_e[(ebase+eL)*ED + k] = a;
    }
    __syncthreads();

    // ------------------------------------------------------------------
    // 5 message-passing layers
    // ------------------------------------------------------------------
    for (int l=0; l<5; l++){
        const float* W1 = gW1 + (long)l*MSG_IN*SD;
        const float* b1 = gb1 + l*SD;
        const float* W2 = gW2 + (long)l*SD*MSG_OUT;
        const float* b2 = gb2 + l*MSG_OUT;

        if (tid < 256) sm->w2p[tid] = W2[tid*MSG_OUT + 320];
        if (tid < 96) sm->npos[tid/3][tid%3] = 0.f;

        // P = s@W1a (pass 1, 16 accs)
        {
            float acc[HROWS];
#pragma unroll
            for (int r=0;r<HROWS;r++) acc[r]=0.f;
            for (int kg=0; kg<64; kg++){
                float wa0=W1[(4*kg+0)*SD+c], wa1=W1[(4*kg+1)*SD+c];
                float wa2=W1[(4*kg+2)*SD+c], wa3=W1[(4*kg+3)*SD+c];
#pragma unroll
                for (int r=0;r<HROWS;r++){
                    float4 v = ((const float4*)&sm->s[r0+r][0])[kg];
                    acc[r] += v.x*wa0 + v.y*wa1 + v.z*wa2 + v.w*wa3;
                }
            }
#pragma unroll
            for (int r=0;r<HROWS;r++) sm->P[r0+r][c]=acc[r];
        }
        // Q = s@W1b + b1 (pass 2, 16 accs) -> global scratch
        {
            float acc[HROWS];
#pragma unroll
            for (int r=0;r<HROWS;r++) acc[r]=0.f;
            for (int kg=0; kg<64; kg++){
                float wb0=W1[(256+4*kg+0)*SD+c], wb1=W1[(256+4*kg+1)*SD+c];
                float wb2=W1[(256+4*kg+2)*SD+c], wb3=W1[(256+4*kg+3)*SD+c];
#pragma unroll
                for (int r=0;r<HROWS;r++){
                    float4 v = ((const float4*)&sm->s[r0+r][0])[kg];
                    acc[r] += v.x*wb0 + v.y*wb1 + v.z*wb2 + v.w*wb3;
                }
            }
            float bb = b1[c];
#pragma unroll
            for (int r=0;r<HROWS;r++) Qg[(r0+r)*SD + c] = acc[r]+bb;
        }
        __syncthreads();

        // per-layer packed constants for [B] (col-pair 2p,2p+1)
        const u64 w1d2 = *(const u64*)&W1[544*SD + 2*p];
        const u64 w1e2 = *(const u64*)&W1[545*SD + 2*p];
        const float b2p = __ldg(&b2[320]);
        const float* wt  = g_w2t + l*8192 + lane*4;    // for [C2]
        const float* W1c = W1 + 512*SD;                // e-part of W1 (global, L1-hot)

        for (int j=0; j<NPER; j++){
            // [A] fold prev pdpart into npos; stage e rows (duplicated) + geometry
            if (j>0 && tid<3){
                float sum=0.f;
#pragma unroll
                for (int w=0;w<16;w++) sum += sm->pdpart[w][tid];
                sm->npos[j-1][tid] += sum;
            }
            for (int idx = tid; idx < NPER*ED; idx += NT){
                int i = idx>>5, k = idx&31;
                float v = 0.f;
                if (i != j){
                    int eL = i*31 + j - (j>i);
                    v = g_e[(ebase+eL)*ED + k];
                }
                *(float2*)&sm->esm2[i][2*k] = make_float2(v, v);
            }
            if (tid < NPER){
                int i = tid;
                float pix=sm->pos[i][0], piy=sm->pos[i][1], piz=sm->pos[i][2];
                float pjx=sm->pos[j][0], pjy=sm->pos[j][1], pjz=sm->pos[j][2];
                float rx=pjx-pix, ry=pjy-piy, rz=pjz-piz;
                float rr = rx*rx + ry*ry + rz*rz;
                float d  = sqrtf(fmaxf(rr, 1e-6f));
                float inv = 1.f/(1.f + d);
                sm->dbuf[i] = d;
                sm->abuf[i] = pix*pjx + piy*pjy + piz*pjz;
                if (i == j){ rx=0.f; ry=0.f; rz=0.f; }
                sm->rnb[i][0]=rx*inv; sm->rnb[i][1]=ry*inv; sm->rnb[i][2]=rz*inv;
            }
            __syncthreads();

            // [B] hdn = silu(P[i]+Q[j]+e@W1c+d*w1d+a*w1e), packed f32x2
            {
                u64 acc[8];
                const u64 Q2 = __ldg((const u64*)&Qg[j*SD + 2*p]);
#pragma unroll
                for (int r=0;r<8;r++){
                    int i = rq + r;
                    u64 t = add2(*(const u64*)&sm->P[i][2*p], Q2);
                    t = fma2(dup2(sm->dbuf[i]), w1d2, t);
                    t = fma2(dup2(sm->abuf[i]), w1e2, t);
                    acc[r] = t;
                }
#pragma unroll 4
                for (int k2=0;k2<16;k2++){
                    u64 w0 = __ldg((const u64*)&W1c[(2*k2  )*SD + 2*p]);
                    u64 w1 = __ldg((const u64*)&W1c[(2*k2+1)*SD + 2*p]);
#pragma unroll
                    for (int r=0;r<8;r++){
                        const ulonglong2 e2 = *(const ulonglong2*)&sm->esm2[rq+r][4*k2];
                        acc[r] = fma2(e2.x, w0, acc[r]);
                        acc[r] = fma2(e2.y, w1, acc[r]);
                    }
                }
                float s0x=0.f, s0y=0.f;
#pragma unroll
                for (int r=0;r<8;r++){
                    int i = rq + r;
                    float hx,hy; unpack2(acc[r],hx,hy);
                    hx = silu_f(hx); hy = silu_f(hy);
                    if (i==j){ hx=0.f; hy=0.f; }
                    *(float2*)&sm->hdn[i][2*p] = make_float2(hx,hy);
                    s0x += hx; s0y += hy;
                }
                *(float2*)&sm->s0q[q4][2*p] = make_float2(s0x,s0y);
            }
            __syncthreads();

            // [C0] combine partial sums into S0 row j (global scratch)
            if (tid < 256)
                S0g[j*SD + tid] = sm->s0q[0][tid] + sm->s0q[1][tid]
                                + sm->s0q[2][tid] + sm->s0q[3][tid];

            // [C1] pos scalars: t_e = hdn.w2p ; pdpart = sum rn*(t+b2p)
            {
                float pdx=0.f, pdy=0.f, pdz=0.f;
#pragma unroll
                for (int r=0;r<2;r++){
                    int i = wrp + 16*r;
                    float part = 0.f;
#pragma unroll
                    for (int m=0;m<8;m++)
                        part += sm->hdn[i][lane+32*m] * sm->w2p[lane+32*m];
#pragma unroll
                    for (int off=16; off>0; off>>=1)
                        part += __shfl_xor_sync(0xffffffffu, part, off);
                    if (lane==0){
                        float t = part + b2p;
                        pdx += sm->rnb[i][0]*t;
                        pdy += sm->rnb[i][1]*t;
                        pdz += sm->rnb[i][2]*t;
                    }
                }
                if (lane==0){ sm->pdpart[wrp][0]=pdx; sm->pdpart[wrp][1]=pdy; sm->pdpart[wrp][2]=pdz; }
            }
            // [C2] e update: e += hdn @ W2e + b2e, packed f32x2, coalesced weights
            {
                const int k = lane;
                const int i0=wrp, i1=wrp+16;
                u64 a0 = 0ULL, a1 = 0ULL;
#pragma unroll 8
                for (int c4=0;c4<64;c4++){
                    ulonglong2 h0 = *(const ulonglong2*)&sm->hdn[i0][4*c4];
                    ulonglong2 h1 = *(const ulonglong2*)&sm->hdn[i1][4*c4];
                    ulonglong2 ww = *(const ulonglong2*)&wt[c4*128];
                    a0 = fma2(h0.x, ww.x, a0); a0 = fma2(h0.y, ww.y, a0);
                    a1 = fma2(h1.x, ww.x, a1); a1 = fma2(h1.y, ww.y, a1);
                }
                float bk = __ldg(&b2[321+k]);
                float x0,y0,x1,y1;
                unpack2(a0,x0,y0); unpack2(a1,x1,y1);
                float v0 = x0+y0+bk, v1 = x1+y1+bk;
                if (i0 != j){
                    int eL = i0*31 + j - (j>i0);
                    g_e[(ebase+eL)*ED + k] = v0 + sm->esm2[i0][2*k];
                }
                if (i1 != j){
                    int eL = i1*31 + j - (j>i1);
                    g_e[(ebase+eL)*ED + k] = v1 + sm->esm2[i1][2*k];
                }
            }
            __syncthreads();
        } // j

        if (tid<3){
            float sum=0.f;
#pragma unroll
            for (int w=0;w<16;w++) sum += sm->pdpart[w][tid];
            sm->npos[31][tid] += sum;
        }
        // s += (S0 @ W2s)/31 + b2s     (S0 broadcast from global scratch)
        {
            float acc[HROWS];
#pragma unroll
            for (int r=0;r<HROWS;r++) acc[r]=0.f;
            for (int kg=0; kg<64; kg++){
                float w0=W2[(4*kg+0)*MSG_OUT+c], w1=W2[(4*kg+1)*MSG_OUT+c];
                float w2v=W2[(4*kg+2)*MSG_OUT+c], w3=W2[(4*kg+3)*MSG_OUT+c];
#pragma unroll
                for (int r=0;r<HROWS;r++){
                    const float4 v = __ldg((const float4*)&S0g[(r0+r)*SD + 4*kg]);
                    acc[r] += v.x*w0 + v.y*w1 + v.z*w2v + v.w*w3;
                }
            }
            __syncthreads();   // npos[31] written; everyone done with this layer's buffers
            float b2s = b2[c];
#pragma unroll
            for (int r=0;r<HROWS;r++)
                sm->s[r0+r][c] += acc[r]*(1.f/31.f) + b2s;
        }
        if (tid<96){
            int i = tid/3, cc = tid%3;
            sm->pos[i][cc] += sm->npos[i][cc]*(1.f/31.f);
        }
        __syncthreads();
    } // layers

    // ------------------------------------------------------------------
    // atoms = silu(s@Wh1+bh1)@Wh2+bh2 ; pos out
    // ------------------------------------------------------------------
    {
        float acc[HROWS];
#pragma unroll
        for (int r=0;r<HROWS;r++) acc[r]=0.f;
        for (int kg=0; kg<64; kg++){
            float w0=Wh1[(4*kg+0)*SD+c], w1=Wh1[(4*kg+1)*SD+c];
            float w2v=Wh1[(4*kg+2)*SD+c], w3=Wh1[(4*kg+3)*SD+c];
#pragma unroll
            for (int r=0;r<HROWS;r++){
                float4 v = ((const float4*)&sm->s[r0+r][0])[kg];
                acc[r] += v.x*w0 + v.y*w1 + v.z*w2v + v.w*w3;
            }
        }
        float bb = bh1[c];
#pragma unroll
        for (int r=0;r<HROWS;r++) sm->P[r0+r][c] = silu_f(acc[r]+bb);
    }
    __syncthreads();
    for (int o = tid; o < NPER*16; o += NT){
        int i = o>>4, cc = o&15;
        float a = bh2[cc];
        for (int k=0;k<SD;k++) a += sm->P[i][k]*Wh2[k*16+cc];
        outA[(nodeBase+i)*16+cc] = a;
    }
    if (tid < 96){
        int i = tid/3, cc = tid%3;
        outP[(nodeBase+i)*3+cc] = sm->pos[i][cc];
    }
    __syncthreads();

    // ------------------------------------------------------------------
    // bonds: bP = s@We1s (per node); per edge: silu(bP_i+bP_j+e@We1e+d*w288+be1)@We2+be2
    // ------------------------------------------------------------------
    float* bP = &sm->hdn[0][0];          // 32 x 128
    {
        const int c128 = tid & 127;
        const int grp  = tid >> 7;       // 0..3, rows grp*8 .. grp*8+7
        float acc[8];
#pragma unroll
        for (int r=0;r<8;r++) acc[r]=0.f;
        for (int kg=0; kg<64; kg++){
            float w0=We1[(4*kg+0)*128+c128], w1=We1[(4*kg+1)*128+c128];
            float w2v=We1[(4*kg+2)*128+c128], w3=We1[(4*kg+3)*128+c128];
#pragma unroll
            for (int r=0;r<8;r++){
                float4 v = ((const float4*)&sm->s[grp*8+r][0])[kg];
                acc[r] += v.x*w0 + v.y*w1 + v.z*w2v + v.w*w3;
            }
        }
#pragma unroll
        for (int r=0;r<8;r++) bP[(grp*8+r)*128 + c128] = acc[r];
    }
    float* We1e_s = &sm->P[0][0];        // 32 x 128 (16KB, P rows 0..15)
    for (int idx = tid; idx < 32*128; idx += NT)
        We1e_s[idx] = We1[(256 + (idx>>7))*128 + (idx&127)];
    __syncthreads();

    float* bh = &sm->P[16][0];           // 16 x 128 (8KB, P rows 16..23)
    float* ebuf = &sm->esm2[0][0];       // 16 x 32 scratch
    {
        const int c128 = tid & 127;
        const int grp  = tid >> 7;       // 0..3
        const float w288 = We1[288*128 + c128];
        const float bbe  = be1[c128];
        for (int pblk=0; pblk<62; pblk++){
            for (int idx = tid; idx < 16*ED; idx += NT){
                int q = idx>>5, k = idx&31;
                int eL = pblk*16 + q;
                ebuf[q*32+k] = g_e[(ebase+eL)*ED + k];
            }
            if (tid < 16){
                int eL = pblk*16 + tid;
                int i = eL/31, jj = eL - i*31; int j = jj + (jj>=i);
                float rx=sm->pos[j][0]-sm->pos[i][0];
                float ry=sm->pos[j][1]-sm->pos[i][1];
                float rz=sm->pos[j][2]-sm->pos[i][2];
                sm->dbuf[tid] = sqrtf(fmaxf(rx*rx+ry*ry+rz*rz, 1e-6f));
            }
            __syncthreads();
#pragma unroll
            for (int qq=0; qq<4; qq++){
                int q = grp*4 + qq;
                int eL = pblk*16 + q;
                int i = eL/31, jj = eL - i*31; int j = jj + (jj>=i);
                float a = bbe + bP[i*128+c128] + bP[j*128+c128] + sm->dbuf[q]*w288;
#pragma unroll
                for (int kg=0; kg<8; kg++){
                    float4 e4 = ((const float4*)&ebuf[q*32])[kg];
                    a += e4.x*We1e_s[(4*kg+0)*128+c128] + e4.y*We1e_s[(4*kg+1)*128+c128]
                       + e4.z*We1e_s[(4*kg+2)*128+c128] + e4.w*We1e_s[(4*kg+3)*128+c128];
                }
                bh[q*128+c128] = silu_f(a);
            }
            __syncthreads();
            {   // warp wrp handles edge wrp of this chunk
                int qq = wrp;
                int eL = pblk*16 + qq;
#pragma unroll
                for (int b=0;b<5;b++){
                    float part = 0.f;
#pragma unroll
                    for (int m=0;m<4;m++){
                        int cc = lane + 32*m;
                        part += bh[qq*128+cc] * We2[cc*5+b];
                    }
#pragma unroll
                    for (int off=16; off>0; off>>=1)
                        part += __shfl_xor_sync(0xffffffffu, part, off);
                    if (lane==0) outB[(ebase+eL)*5+b] = part + be2[b];
                }
            }
            __syncthreads();
        }
    }
}

extern "C" void kernel_launch(void* const* d_in, const int* in_sizes, int n_in,
                              void* d_out, int out_size)
{
    const float* x    = (const float*)d_in[0];
    const float* z    = (const float*)d_in[1];
    const float* rot  = (const float*)d_in[2];
    // d_in[3] edge_index (int64) unused — structure is static block-dense
    const float* eattr= (const float*)d_in[4];
    // d_in[5] batch (int64) unused
    const float* Wam  = (const float*)d_in[6];
    const float* bam  = (const float*)d_in[7];
    const float* Wbm  = (const float*)d_in[8];
    const float* bbm  = (const float*)d_in[9];
    const float* gW1  = (const float*)d_in[10];
    const float* gb1  = (const float*)d_in[11];
    const float* gW2  = (const float*)d_in[12];
    const float* gb2  = (const float*)d_in[13];
    const float* Wh1  = (const float*)d_in[14];
    const float* bh1  = (const float*)d_in[15];
    const float* Wh2  = (const float*)d_in[16];
    const float* bh2  = (const float*)d_in[17];
    const float* We1  = (const float*)d_in[18];
    const float* be1  = (const float*)d_in[19];
    const float* We2  = (const float*)d_in[20];
    const float* be2  = (const float*)d_in[21];

    float* out  = (float*)d_out;
    float* outA = out;                                   // atoms: N x 16
    float* outB = out + (long)NNODE*16;                  // bonds: E x 5
    float* outP = out + (long)NNODE*16 + (long)ETOT*5;   // pos:   N x 3

    prep_kernel<<<160, 256>>>(gW2);

    const size_t shmem = sizeof(SM);
    cudaFuncSetAttribute(dec_kernel, cudaFuncAttributeMaxDynamicSharedMemorySize, (int)shmem);
    dec_kernel<<<NMOL, NT, shmem>>>(x,z,rot,eattr,Wam,bam,Wbm,bbm,
                                    gW1,gb1,gW2,gb2,Wh1,bh1,Wh2,bh2,
                                    We1,be1,We2,be2,outA,outB,outP);
}